// round 16
// baseline (speedup 1.0000x reference)
#include <cuda_runtime.h>
#include <cuda_fp16.h>
#include <cstdint>

// ---------------- problem constants ----------------
#define Cdim  512
#define NHd   16
#define HDd   32
#define Ltok  4096
#define Mrows 65536
#define HIDd  2048

// ---------------- scratch (device globals) --------------------------------
__device__ __half g_xw[(size_t)Mrows * Cdim];       // packed layout
__device__ __half g_qkvh[(size_t)Mrows * 3 * Cdim]; // natural layout fp16
__device__ __half g_at[(size_t)Mrows * Cdim];       // packed layout
__device__ float  g_x2[(size_t)Mrows * Cdim];
__device__ __half g_xm[(size_t)Mrows * Cdim];       // packed layout
__device__ __half g_h [(size_t)Mrows * HIDd];       // packed layout
__device__ __half g_wq[1536 * 512];
__device__ __half g_wp[512 * 512];
__device__ __half g_w1[2048 * 512];
__device__ __half g_w2[512 * 2048];

// windowed row r -> (batch, natural token l)
__device__ __forceinline__ void win_to_nat(int r, int& bt, int& l) {
    int wb = r >> 6, n = r & 63;
    bt = wb >> 6;
    int wi = wb & 63;
    int hb = wi >> 3, wk = wi & 7;
    l = (((hb << 3) + (n >> 3)) << 6) + (wk << 3) + (n & 7);
}

// K-blocked packed layout with baked-in ldmatrix swizzle.
__device__ __forceinline__ size_t packed_off(int row, int k, int RowsTotal) {
    int kt = k >> 5;
    int ch = (k >> 3) & 3;
    int c7 = (((row & 1) << 2) | ch) ^ ((row >> 1) & 7);
    return (((size_t)kt * RowsTotal + (row & ~1)) << 5) + (c7 << 3) + (k & 7);
}

// ---------------- PTX helpers ---------------------------------------------
__device__ __forceinline__ uint32_t smem_u32(const void* p) {
    uint32_t a;
    asm("{ .reg .u64 t; cvta.to.shared.u64 t, %1; cvt.u32.u64 %0, t; }" : "=r"(a) : "l"(p));
    return a;
}
__device__ __forceinline__ void mbar_init(uint32_t m, uint32_t cnt) {
    asm volatile("mbarrier.init.shared.b64 [%0], %1;" :: "r"(m), "r"(cnt) : "memory");
}
__device__ __forceinline__ void mbar_wait(uint32_t m, uint32_t parity) {
    asm volatile(
        "{\n\t.reg .pred P;\n\t"
        "W_%=:\n\t"
        "mbarrier.try_wait.parity.acquire.cta.shared::cta.b64 P, [%0], %1, 0x989680;\n\t"
        "@P bra D_%=;\n\t"
        "bra W_%=;\n\t"
        "D_%=:\n\t}"
        :: "r"(m), "r"(parity) : "memory");
}
__device__ __forceinline__ void mbar_arrive(uint32_t m) {
    asm volatile("mbarrier.arrive.shared.b64 _, [%0];" :: "r"(m) : "memory");
}
__device__ __forceinline__ void mbar_expect_tx(uint32_t m, uint32_t bytes) {
    asm volatile("mbarrier.arrive.expect_tx.shared.b64 _, [%0], %1;"
                 :: "r"(m), "r"(bytes) : "memory");
}
__device__ __forceinline__ void bulk_g2s(uint32_t dst, const void* src,
                                         uint32_t bytes, uint32_t mbar) {
    asm volatile(
        "cp.async.bulk.shared::cluster.global.mbarrier::complete_tx::bytes [%0], [%1], %2, [%3];"
        :: "r"(dst), "l"(src), "r"(bytes), "r"(mbar) : "memory");
}

__device__ __forceinline__ uint32_t swz(uint32_t off) {
    return off ^ (((off >> 7) & 7) << 4);
}
__device__ __forceinline__ void ldmx4(uint32_t addr, uint32_t& r0, uint32_t& r1,
                                      uint32_t& r2, uint32_t& r3) {
    asm volatile("ldmatrix.sync.aligned.m8n8.x4.shared.b16 {%0,%1,%2,%3}, [%4];"
                 : "=r"(r0), "=r"(r1), "=r"(r2), "=r"(r3) : "r"(addr));
}
__device__ __forceinline__ void mma16816(float* c, const uint32_t* a, const uint32_t* b) {
    asm volatile(
        "mma.sync.aligned.m16n8k16.row.col.f32.f16.f16.f32 "
        "{%0,%1,%2,%3}, {%4,%5,%6,%7}, {%8,%9}, {%0,%1,%2,%3};"
        : "+f"(c[0]), "+f"(c[1]), "+f"(c[2]), "+f"(c[3])
        : "r"(a[0]), "r"(a[1]), "r"(a[2]), "r"(a[3]), "r"(b[0]), "r"(b[1]));
}

// ---------------- mma.sync GEMM: 128x128 tile, 3 CTAs/SM ------------------
#define STG       16384          // A 8K | W 8K
#define NSTAGE    4
#define SMEM_TOT  (1024 + NSTAGE * STG)

#define EP_BIAS 0
#define EP_GELU 1
#define EP_PROJ 2
#define EP_ADD  3

__device__ __forceinline__ void issue_stage(
    uint32_t sbase, int kn, int b, int Nout, int bm0, int bn0,
    const __half* __restrict__ A, const __half* __restrict__ W)
{
    const uint32_t mbar = sbase + b * 8;
    const uint32_t sb = sbase + 1024 + b * STG;
    mbar_expect_tx(mbar, 16384u);
    const size_t aoff = ((size_t)kn * Mrows + bm0) << 6;   // bytes
    const size_t woff = ((size_t)kn * Nout + bn0) << 6;
    bulk_g2s(sb,        (const char*)A + aoff, 8192, mbar);
    bulk_g2s(sb + 8192, (const char*)W + woff, 8192, mbar);
}

template<int EPI>
__global__ void __launch_bounds__(128, 3) tgemm(
    int K, int Nout,
    const __half* __restrict__ A, const __half* __restrict__ W,
    const float* __restrict__ bias, const float* __restrict__ res,
    float* __restrict__ outf, __half* __restrict__ outh)
{
    extern __shared__ char smem[];
    const uint32_t sbase = smem_u32(smem);
    const int tid  = threadIdx.x;
    const int bn0  = blockIdx.x * 128;
    const int bm0  = blockIdx.y * 128;
    const int warp = tid >> 5, lane = tid & 31;
    const int wm = (warp >> 1) * 64;
    const int wn = (warp & 1) * 64;

    if (tid == 0) {
        #pragma unroll
        for (int s = 0; s < NSTAGE; s++) {
            mbar_init(sbase + s * 8, 1);
            mbar_init(sbase + 32 + s * 8, 128);
        }
        asm volatile("fence.proxy.async.shared::cta;" ::: "memory");
    }
    __syncthreads();

    const int nk = K >> 5;
    if (tid == 0) {
        issue_stage(sbase, 0, 0, Nout, bm0, bn0, A, W);
        issue_stage(sbase, 1, 1, Nout, bm0, bn0, A, W);
        issue_stage(sbase, 2, 2, Nout, bm0, bn0, A, W);
        issue_stage(sbase, 3, 3, Nout, bm0, bn0, A, W);
    }

    float acc[4][8][4];
    #pragma unroll
    for (int mf = 0; mf < 4; mf++)
        #pragma unroll
        for (int nf = 0; nf < 8; nf++)
            #pragma unroll
            for (int u = 0; u < 4; u++) acc[mf][nf][u] = 0.0f;

    const int rA = wm + (lane & 15);
    const int rB = wn + (lane & 15);
    const int cb = lane >> 4;

    for (int kt = 0; kt < nk; kt++) {
        const int b = kt & 3;
        const int cyc = kt >> 2;
        mbar_wait(sbase + b * 8, cyc & 1);

        const uint32_t sg = sbase + 1024 + b * STG;
        const uint32_t at = sg;
        const uint32_t wt = sg + 8192;
        #pragma unroll
        for (int kf = 0; kf < 2; kf++) {
            const int ch = kf * 2 + cb;
            uint32_t a[4][4];
            #pragma unroll
            for (int mf = 0; mf < 4; mf++)
                ldmx4(at + swz((rA + mf * 16) * 64 + ch * 16),
                      a[mf][0], a[mf][1], a[mf][2], a[mf][3]);
            uint32_t b2[8][2];
            #pragma unroll
            for (int n2 = 0; n2 < 4; n2++) {
                uint32_t r0, r1, r2, r3;
                ldmx4(wt + swz((rB + n2 * 16) * 64 + ch * 16), r0, r1, r2, r3);
                b2[2 * n2][0] = r0; b2[2 * n2][1] = r2;
                b2[2 * n2 + 1][0] = r1; b2[2 * n2 + 1][1] = r3;
            }
            #pragma unroll
            for (int mf = 0; mf < 4; mf++)
                #pragma unroll
                for (int nf = 0; nf < 8; nf++)
                    mma16816(acc[mf][nf], a[mf], b2[nf]);
        }
        mbar_arrive(sbase + 32 + b * 8);
        if (tid == 0 && kt + NSTAGE < nk) {
            mbar_wait(sbase + 32 + b * 8, cyc & 1);
            issue_stage(sbase, kt + NSTAGE, b, Nout, bm0, bn0, A, W);
        }
    }

    // ---------------- epilogue ----------------
    const int g = lane >> 2, q = lane & 3;
    #pragma unroll
    for (int mf = 0; mf < 4; mf++) {
        const int row0 = bm0 + wm + mf * 16 + g;
        const int row1 = row0 + 8;
        size_t ob0, ob1;
        if (EPI == EP_PROJ) {
            int bt, l;
            win_to_nat(row0, bt, l); ob0 = ((size_t)bt * Ltok + l) * (size_t)Nout;
            win_to_nat(row1, bt, l); ob1 = ((size_t)bt * Ltok + l) * (size_t)Nout;
        } else {
            ob0 = (size_t)row0 * Nout;
            ob1 = (size_t)row1 * Nout;
        }
        #pragma unroll
        for (int nf = 0; nf < 8; nf++) {
            const int col = bn0 + wn + nf * 8 + q * 2;
            const float b0 = bias[col], b1 = bias[col + 1];
            float v00 = acc[mf][nf][0] + b0, v01 = acc[mf][nf][1] + b1;
            float v10 = acc[mf][nf][2] + b0, v11 = acc[mf][nf][3] + b1;
            if (EPI == EP_BIAS) {
                *(__half2*)(outh + ob0 + col) = __halves2half2(__float2half_rn(v00), __float2half_rn(v01));
                *(__half2*)(outh + ob1 + col) = __halves2half2(__float2half_rn(v10), __float2half_rn(v11));
            } else if (EPI == EP_GELU) {
                v00 = 0.5f * v00 * (1.0f + erff(v00 * 0.70710678118654752f));
                v01 = 0.5f * v01 * (1.0f + erff(v01 * 0.70710678118654752f));
                v10 = 0.5f * v10 * (1.0f + erff(v10 * 0.70710678118654752f));
                v11 = 0.5f * v11 * (1.0f + erff(v11 * 0.70710678118654752f));
                size_t p0 = packed_off(row0, col, Mrows);
                size_t p1 = packed_off(row1, col, Mrows);
                *(__half2*)(outh + p0) = __halves2half2(__float2half_rn(v00), __float2half_rn(v01));
                *(__half2*)(outh + p1) = __halves2half2(__float2half_rn(v10), __float2half_rn(v11));
            } else {  // EP_PROJ / EP_ADD: += residual
                float2 r0 = *(const float2*)(res + ob0 + col);
                float2 r1 = *(const float2*)(res + ob1 + col);
                *(float2*)(outf + ob0 + col) = make_float2(v00 + r0.x, v01 + r0.y);
                *(float2*)(outf + ob1 + col) = make_float2(v10 + r1.x, v11 + r1.y);
            }
        }
    }
}

// ---------------- fp32 -> fp16 weight conversion (packed) -----------------
__global__ __launch_bounds__(256) void cvt_w(
    const float* __restrict__ src, __half* __restrict__ dst, int Rows, int K)
{
    int i = blockIdx.x * 256 + threadIdx.x;   // 16B-chunk id
    int cpr = K >> 3;
    int n = i / cpr;
    int kc = (i - n * cpr) << 3;
    const float4* s = (const float4*)(src + (size_t)n * K + kc);
    float4 v0 = s[0], v1 = s[1];
    float vv[8] = { v0.x, v0.y, v0.z, v0.w, v1.x, v1.y, v1.z, v1.w };
    __half h[8];
    #pragma unroll
    for (int u = 0; u < 8; u++) h[u] = __float2half_rn(vv[u]);
    size_t o = packed_off(n, kc, Rows);
    *(uint4*)(dst + o) = *(uint4*)h;
}

// ---------------- LayerNorm: warp-per-row -> fp16 packed ------------------
__global__ __launch_bounds__(256) void ln_kernel(
    const float* __restrict__ x, const float* __restrict__ g,
    const float* __restrict__ b, __half* __restrict__ outh, int windowed)
{
    const int warp = threadIdx.x >> 5, lane = threadIdx.x & 31;
    const int r = blockIdx.x * 8 + warp;
    size_t ibase;
    if (windowed) {
        int bt, l; win_to_nat(r, bt, l);
        ibase = ((size_t)bt * Ltok + l) * Cdim;
    } else {
        ibase = (size_t)r * Cdim;
    }
    float4 v[4];
    float s = 0.0f, sq = 0.0f;
    #pragma unroll
    for (int i = 0; i < 4; i++) {
        v[i] = *(const float4*)(x + ibase + i * 128 + lane * 4);
        s  += v[i].x + v[i].y + v[i].z + v[i].w;
        sq += v[i].x*v[i].x + v[i].y*v[i].y + v[i].z*v[i].z + v[i].w*v[i].w;
    }
    #pragma unroll
    for (int off = 16; off; off >>= 1) {
        s  += __shfl_xor_sync(0xffffffffu, s,  off);
        sq += __shfl_xor_sync(0xffffffffu, sq, off);
    }
    const float mean = s * (1.0f / 512.0f);
    const float var  = sq * (1.0f / 512.0f) - mean * mean;
    const float rstd = rsqrtf(var + 1e-5f);
    #pragma unroll
    for (int i = 0; i < 4; i++) {
        const int col = i * 128 + lane * 4;
        float4 gg = *(const float4*)(g + col);
        float4 bb = *(const float4*)(b + col);
        __half hv[4];
        hv[0] = __float2half_rn((v[i].x - mean) * rstd * gg.x + bb.x);
        hv[1] = __float2half_rn((v[i].y - mean) * rstd * gg.y + bb.y);
        hv[2] = __float2half_rn((v[i].z - mean) * rstd * gg.z + bb.z);
        hv[3] = __float2half_rn((v[i].w - mean) * rstd * gg.w + bb.w);
        *(uint2*)(outh + packed_off(r, col, Mrows)) = *(uint2*)hv;
    }
}

// ---------------- mma-based windowed attention ----------------------------
#define QSCALE 0.17677669529663687f
#define AZC    0.09817477042468103f
#define RDC    0.02454369260617026f

__global__ __launch_bounds__(128) void attn_kernel(
    const __half* __restrict__ qkv, const float* __restrict__ Dp,
    const float* __restrict__ a_p, const float* __restrict__ b_p,
    const float* __restrict__ a_r, const float* __restrict__ b_r,
    __half* __restrict__ outh)
{
    __shared__ __half Qs[2048];    // 64 x 32, swizzled 64B rows
    __shared__ __half Ks[2048];    // 64 x 32, swizzled 64B rows
    __shared__ __half Vt[2048];    // 32 x 64 (transposed), swizzled 128B rows
    __shared__ float csr[15][64];
    __shared__ float ssr[15][64];
    __shared__ float arh[15], brh[15], phs[15];

    const int wb  = blockIdx.x;
    const int h   = blockIdx.y;
    const int tid = threadIdx.x;
    const int warp = tid >> 5, lane = tid & 31;
    const uint32_t qb = smem_u32(Qs), kb = smem_u32(Ks), vb = smem_u32(Vt);

    // ---- stage Q,K (swizzled rows) and V transposed ----
    {
        const int n = tid >> 1, c0 = (tid & 1) * 2;
        const size_t base = ((size_t)(wb * 64 + n)) * 1536 + h * 32;
        #pragma unroll
        for (int cc = 0; cc < 2; cc++) {
            const int ch = c0 + cc;
            uint4 qv = *(const uint4*)(qkv + base + ch * 8);
            *(uint4*)((char*)Qs + swz(n * 64 + ch * 16)) = qv;
            uint4 kv = *(const uint4*)(qkv + base + 512 + ch * 8);
            *(uint4*)((char*)Ks + swz(n * 64 + ch * 16)) = kv;
            uint4 vv = *(const uint4*)(qkv + base + 1024 + ch * 8);
            const __half* vh = (const __half*)&vv;
            #pragma unroll
            for (int u = 0; u < 8; u++) {
                const int d = ch * 8 + u;
                *(__half*)((char*)Vt + swz(d * 128 + n * 2)) = vh[u];
            }
        }
    }
    {
        int bt = wb >> 6, wi = wb & 63, hb = wi >> 3, wk = wi & 7;
        for (int v = tid; v < 960; v += 128) {
            int dyp = v >> 6, jj = v & 63;
            float Dv = Dp[bt * 4096 + (((hb << 3) + (jj >> 3)) << 6) + (wk << 3) + (jj & 7)];
            float ang = (float)(dyp - 7) * Dv * RDC;
            float sn, cs; __sincosf(ang, &sn, &cs);
            csr[dyp][jj] = cs; ssr[dyp][jj] = sn;
        }
    }
    if (tid < 15) {
        arh[tid] = a_r[tid * NHd + h];
        brh[tid] = b_r[tid * NHd + h];
        int dx = tid - 7;
        int ip = dx < 0 ? dx + 15 : dx;
        float azf = (float)dx * AZC;
        float sn, cs; __sincosf(azf, &sn, &cs);
        phs[tid] = a_p[ip * NHd + h] * cs + b_p[ip * NHd + h] * sn;
    }
    __syncthreads();

    // ---- S = Q K^T (warp: rows 16w..16w+15, all 64 cols) ----
    const int rA = (warp << 4) + (lane & 15);
    const int rN = lane & 15;
    const int cb = lane >> 4;
    float acc[8][4];
    #pragma unroll
    for (int nf = 0; nf < 8; nf++)
        #pragma unroll
        for (int u = 0; u < 4; u++) acc[nf][u] = 0.0f;

    #pragma unroll
    for (int kf = 0; kf < 2; kf++) {
        const int ch = kf * 2 + cb;
        uint32_t a[4];
        ldmx4(qb + swz(rA * 64 + ch * 16), a[0], a[1], a[2], a[3]);
        uint32_t b2[8][2];
        #pragma unroll
        for (int n2 = 0; n2 < 4; n2++) {
            uint32_t r0, r1, r2, r3;
            ldmx4(kb + swz((n2 * 16 + rN) * 64 + ch * 16), r0, r1, r2, r3);
            b2[2 * n2][0] = r0; b2[2 * n2][1] = r2;
            b2[2 * n2 + 1][0] = r1; b2[2 * n2 + 1][1] = r3;
        }
        #pragma unroll
        for (int nf = 0; nf < 8; nf++)
            mma16816(acc[nf], a, b2[nf]);
    }

    // ---- scale + bias (frag mapping: rows 16w+g, 16w+g+8; col nf*8+2q(+1)) ----
    const int g = lane >> 2, q = lane & 3;
    const float ph0 = phs[g - 2 * q + 7];
    const float ph1 = phs[g - 2 * q + 6];
    #pragma unroll
    for (int nf = 0; nf < 8; nf++) {
        const int dy0 = 2 * warp - nf;
        const int dyp0 = dy0 + 7, ir0 = dy0 < 0 ? dy0 + 15 : dy0;
        const int dy1 = dy0 + 1;
        const int dyp1 = dy1 + 7, ir1 = dy1 < 0 ? dy1 + 15 : dy1;
        const int jA = nf * 8 + 2 * q, jB = jA + 1;
        acc[nf][0] = acc[nf][0] * QSCALE + ph0 + arh[ir0] * csr[dyp0][jA] + brh[ir0] * ssr[dyp0][jA];
        acc[nf][1] = acc[nf][1] * QSCALE + ph1 + arh[ir0] * csr[dyp0][jB] + brh[ir0] * ssr[dyp0][jB];
        acc[nf][2] = acc[nf][2] * QSCALE + ph0 + arh[ir1] * csr[dyp1][jA] + brh[ir1] * ssr[dyp1][jA];
        acc[nf][3] = acc[nf][3] * QSCALE + ph1 + arh[ir1] * csr[dyp1][jB] + brh[ir1] * ssr[dyp1][jB];
    }

    // ---- softmax (rows owned by one warp; reduce across the 4 q-lanes) ----
    float mx0 = -1e30f, mx1 = -1e30f;
    #pragma unroll
    for (int nf = 0; nf < 8; nf++) {
        mx0 = fmaxf(mx0, fmaxf(acc[nf][0], acc[nf][1]));
        mx1 = fmaxf(mx1, fmaxf(acc[nf][2], acc[nf][3]));
    }
    mx0 = fmaxf(mx0, __shfl_xor_sync(0xffffffffu, mx0, 1));
    mx0 = fmaxf(mx0, __shfl_xor_sync(0xffffffffu, mx0, 2));
    mx1 = fmaxf(mx1, __shfl_xor_sync(0xffffffffu, mx1, 1));
    mx1 = fmaxf(mx1, __shfl_xor_sync(0xffffffffu, mx1, 2));
    float s0 = 0.0f, s1 = 0.0f;
    #pragma unroll
    for (int nf = 0; nf < 8; nf++) {
        acc[nf][0] = __expf(acc[nf][0] - mx0); s0 += acc[nf][0];
        acc[nf][1] = __expf(acc[nf][1] - mx0); s0 += acc[nf][1];
        acc[nf][2] = __expf(acc[nf][2] - mx1); s1 += acc[nf][2];
        acc[nf][3] = __expf(acc[nf][3] - mx1); s1 += acc[nf][3];
    }
    s0 += __shfl_xor_sync(0xffffffffu, s0, 1);
    s0 += __shfl_xor_sync(0xffffffffu, s0, 2);
    s1 += __shfl_xor_sync(0xffffffffu, s1, 1);
    s1 += __shfl_xor_sync(0xffffffffu, s1, 2);
    const float inv0 = 1.0f / s0, inv1 = 1.0f / s1;

    // ---- repack P (C frags -> fp16 A frags) ----
    uint32_t p[4][4];
    #pragma unroll
    for (int kt = 0; kt < 4; kt++) {
        __half2 h0 = __floats2half2_rn(acc[2 * kt][0] * inv0,     acc[2 * kt][1] * inv0);
        __half2 h1 = __floats2half2_rn(acc[2 * kt][2] * inv1,     acc[2 * kt][3] * inv1);
        __half2 h2 = __floats2half2_rn(acc[2 * kt + 1][0] * inv0, acc[2 * kt + 1][1] * inv0);
        __half2 h3 = __floats2half2_rn(acc[2 * kt + 1][2] * inv1, acc[2 * kt + 1][3] * inv1);
        p[kt][0] = *(uint32_t*)&h0; p[kt][1] = *(uint32_t*)&h1;
        p[kt][2] = *(uint32_t*)&h2; p[kt][3] = *(uint32_t*)&h3;
    }

    // ---- O = P V (B frags from V^T) ----
    float oacc[4][4];
    #pragma unroll
    for (int nf2 = 0; nf2 < 4; nf2++)
        #pragma unroll
        for (int u = 0; u < 4; u++) oacc[nf2][u] = 0.0f;
    #pragma unroll
    for (int kt = 0; kt < 4; kt++) {
        uint32_t bv[4][2];
        #pragma unroll
        for (int n2 = 0; n2 < 2; n2++) {
            uint32_t r0, r1, r2, r3;
            ldmx4(vb + swz((n2 * 16 + rN) * 128 + (kt * 2 + cb) * 16), r0, r1, r2, r3);
            bv[2 * n2][0] = r0; bv[2 * n2][1] = r2;
            bv[2 * n2 + 1][0] = r1; bv[2 * n2 + 1][1] = r3;
        }
        #pragma unroll
        for (int nf2 = 0; nf2 < 4; nf2++)
            mma16816(oacc[nf2], p[kt], bv[nf2]);
    }

    // ---- store O -> packed fp16 ----
    const int i0 = (warp << 4) + g;
    const int row0 = wb * 64 + i0, row1 = row0 + 8;
    #pragma unroll
    for (int nf2 = 0; nf2 < 4; nf2++) {
        const int d = h * 32 + nf2 * 8 + 2 * q;
        *(__half2*)(outh + packed_off(row0, d, Mrows)) =
            __floats2half2_rn(oacc[nf2][0], oacc[nf2][1]);
        *(__half2*)(outh + packed_off(row1, d, Mrows)) =
            __floats2half2_rn(oacc[nf2][2], oacc[nf2][3]);
    }
}

// ---------------- launch -------------------------------------------------
extern "C" void kernel_launch(void* const* d_in, const int* in_sizes, int n_in,
                              void* d_out, int out_size) {
    (void)in_sizes; (void)n_in; (void)out_size;
    const float* x      = (const float*)d_in[0];
    const float* D      = (const float*)d_in[1];
    const float* n1g    = (const float*)d_in[2];
    const float* n1b    = (const float*)d_in[3];
    const float* qkv_w  = (const float*)d_in[4];
    const float* qkv_b  = (const float*)d_in[5];
    const float* proj_w = (const float*)d_in[6];
    const float* proj_b = (const float*)d_in[7];
    const float* a_p    = (const float*)d_in[8];
    const float* b_p    = (const float*)d_in[9];
    const float* a_r    = (const float*)d_in[10];
    const float* b_r    = (const float*)d_in[11];
    const float* n2g    = (const float*)d_in[12];
    const float* n2b    = (const float*)d_in[13];
    const float* fc1_w  = (const float*)d_in[14];
    const float* fc1_b  = (const float*)d_in[15];
    const float* fc2_w  = (const float*)d_in[16];
    const float* fc2_b  = (const float*)d_in[17];
    float* out = (float*)d_out;

    __half *xw, *qkvh, *at, *xm, *hb, *wq, *wp, *w1, *w2;
    float *x2;
    cudaGetSymbolAddress((void**)&xw, g_xw);
    cudaGetSymbolAddress((void**)&qkvh, g_qkvh);
    cudaGetSymbolAddress((void**)&at, g_at);
    cudaGetSymbolAddress((void**)&xm, g_xm);
    cudaGetSymbolAddress((void**)&hb, g_h);
    cudaGetSymbolAddress((void**)&wq, g_wq);
    cudaGetSymbolAddress((void**)&wp, g_wp);
    cudaGetSymbolAddress((void**)&w1, g_w1);
    cudaGetSymbolAddress((void**)&w2, g_w2);
    cudaGetSymbolAddress((void**)&x2, g_x2);

    cudaFuncSetAttribute(tgemm<EP_BIAS>, cudaFuncAttributeMaxDynamicSharedMemorySize, SMEM_TOT);
    cudaFuncSetAttribute(tgemm<EP_GELU>, cudaFuncAttributeMaxDynamicSharedMemorySize, SMEM_TOT);
    cudaFuncSetAttribute(tgemm<EP_PROJ>, cudaFuncAttributeMaxDynamicSharedMemorySize, SMEM_TOT);
    cudaFuncSetAttribute(tgemm<EP_ADD>,  cudaFuncAttributeMaxDynamicSharedMemorySize, SMEM_TOT);

    // weight conversions into packed layout
    cvt_w<<<(1536 * 512 / 8) / 256, 256>>>(qkv_w,  wq, 1536, 512);
    cvt_w<<<(512 * 512 / 8)  / 256, 256>>>(proj_w, wp, 512,  512);
    cvt_w<<<(2048 * 512 / 8) / 256, 256>>>(fc1_w,  w1, 2048, 512);
    cvt_w<<<(512 * 2048 / 8) / 256, 256>>>(fc2_w,  w2, 512,  2048);

    // 1) LN1 + window partition -> packed fp16
    ln_kernel<<<Mrows / 8, 256>>>(x, n1g, n1b, xw, 1);
    // 2) QKV GEMM -> fp16 natural
    tgemm<EP_BIAS><<<dim3(1536 / 128, Mrows / 128), 128, SMEM_TOT>>>(
        512, 1536, xw, wq, qkv_b, nullptr, nullptr, qkvh);
    // 3) mma windowed attention -> packed fp16
    attn_kernel<<<dim3(1024, 16), 128>>>(qkvh, D, a_p, b_p, a_r, b_r, at);
    // 4) proj GEMM + window reverse + residual
    tgemm<EP_PROJ><<<dim3(512 / 128, Mrows / 128), 128, SMEM_TOT>>>(
        512, 512, at, wp, proj_b, x, x2, nullptr);
    // 5) LN2 -> packed fp16
    ln_kernel<<<Mrows / 8, 256>>>(x2, n2g, n2b, xm, 0);
    // 6) fc1 + GELU -> packed fp16
    tgemm<EP_GELU><<<dim3(2048 / 128, Mrows / 128), 128, SMEM_TOT>>>(
        512, 2048, xm, w1, fc1_b, nullptr, nullptr, hb);
    // 7) fc2 + residual -> output
    tgemm<EP_ADD><<<dim3(512 / 128, Mrows / 128), 128, SMEM_TOT>>>(
        2048, 512, hb, w2, fc2_b, x2, out, nullptr);
}

// round 17
// speedup vs baseline: 1.1347x; 1.1347x over previous
#include <cuda_runtime.h>
#include <cuda_fp16.h>
#include <cstdint>

// ---------------- problem constants ----------------
#define Cdim  512
#define NHd   16
#define HDd   32
#define Ltok  4096
#define Mrows 65536
#define HIDd  2048

// ---------------- scratch (device globals) --------------------------------
__device__ __half g_xw[(size_t)Mrows * Cdim];       // packed layout
__device__ __half g_qkvh[(size_t)Mrows * 3 * Cdim]; // natural layout fp16
__device__ __half g_at[(size_t)Mrows * Cdim];       // packed layout
__device__ float  g_x2[(size_t)Mrows * Cdim];
__device__ __half g_xm[(size_t)Mrows * Cdim];       // packed layout
__device__ __half g_h [(size_t)Mrows * HIDd];       // packed layout
__device__ __half g_wq[1536 * 512];
__device__ __half g_wp[512 * 512];
__device__ __half g_w1[2048 * 512];
__device__ __half g_w2[512 * 2048];

// windowed row r -> (batch, natural token l)
__device__ __forceinline__ void win_to_nat(int r, int& bt, int& l) {
    int wb = r >> 6, n = r & 63;
    bt = wb >> 6;
    int wi = wb & 63;
    int hb = wi >> 3, wk = wi & 7;
    l = (((hb << 3) + (n >> 3)) << 6) + (wk << 3) + (n & 7);
}

// K-blocked packed layout with baked-in ldmatrix swizzle.
__device__ __forceinline__ size_t packed_off(int row, int k, int RowsTotal) {
    int kt = k >> 5;
    int ch = (k >> 3) & 3;
    int c7 = (((row & 1) << 2) | ch) ^ ((row >> 1) & 7);
    return (((size_t)kt * RowsTotal + (row & ~1)) << 5) + (c7 << 3) + (k & 7);
}

// ---------------- PTX helpers ---------------------------------------------
__device__ __forceinline__ uint32_t smem_u32(const void* p) {
    uint32_t a;
    asm("{ .reg .u64 t; cvta.to.shared.u64 t, %1; cvt.u32.u64 %0, t; }" : "=r"(a) : "l"(p));
    return a;
}
__device__ __forceinline__ void mbar_init(uint32_t m, uint32_t cnt) {
    asm volatile("mbarrier.init.shared.b64 [%0], %1;" :: "r"(m), "r"(cnt) : "memory");
}
__device__ __forceinline__ void mbar_wait(uint32_t m, uint32_t parity) {
    asm volatile(
        "{\n\t.reg .pred P;\n\t"
        "W_%=:\n\t"
        "mbarrier.try_wait.parity.acquire.cta.shared::cta.b64 P, [%0], %1, 0x989680;\n\t"
        "@P bra D_%=;\n\t"
        "bra W_%=;\n\t"
        "D_%=:\n\t}"
        :: "r"(m), "r"(parity) : "memory");
}
__device__ __forceinline__ void mbar_arrive(uint32_t m) {
    asm volatile("mbarrier.arrive.shared.b64 _, [%0];" :: "r"(m) : "memory");
}
__device__ __forceinline__ void mbar_expect_tx(uint32_t m, uint32_t bytes) {
    asm volatile("mbarrier.arrive.expect_tx.shared.b64 _, [%0], %1;"
                 :: "r"(m), "r"(bytes) : "memory");
}
__device__ __forceinline__ void bulk_g2s(uint32_t dst, const void* src,
                                         uint32_t bytes, uint32_t mbar) {
    asm volatile(
        "cp.async.bulk.shared::cluster.global.mbarrier::complete_tx::bytes [%0], [%1], %2, [%3];"
        :: "r"(dst), "l"(src), "r"(bytes), "r"(mbar) : "memory");
}

__device__ __forceinline__ uint32_t swz(uint32_t off) {
    return off ^ (((off >> 7) & 7) << 4);
}
__device__ __forceinline__ void ldmx4(uint32_t addr, uint32_t& r0, uint32_t& r1,
                                      uint32_t& r2, uint32_t& r3) {
    asm volatile("ldmatrix.sync.aligned.m8n8.x4.shared.b16 {%0,%1,%2,%3}, [%4];"
                 : "=r"(r0), "=r"(r1), "=r"(r2), "=r"(r3) : "r"(addr));
}
__device__ __forceinline__ void mma16816(float* c, const uint32_t* a, const uint32_t* b) {
    asm volatile(
        "mma.sync.aligned.m16n8k16.row.col.f32.f16.f16.f32 "
        "{%0,%1,%2,%3}, {%4,%5,%6,%7}, {%8,%9}, {%0,%1,%2,%3};"
        : "+f"(c[0]), "+f"(c[1]), "+f"(c[2]), "+f"(c[3])
        : "r"(a[0]), "r"(a[1]), "r"(a[2]), "r"(a[3]), "r"(b[0]), "r"(b[1]));
}

// ---------------- mma.sync GEMM: 128x128 tile, 2 CTAs/SM (champion) -------
#define STG       16384          // A 8K | W 8K
#define NSTAGE    4
#define SMEM_TOT  (1024 + NSTAGE * STG)

#define EP_BIAS 0
#define EP_GELU 1
#define EP_PROJ 2
#define EP_ADD  3

__device__ __forceinline__ void issue_stage(
    uint32_t sbase, int kn, int b, int Nout, int bm0, int bn0,
    const __half* __restrict__ A, const __half* __restrict__ W)
{
    const uint32_t mbar = sbase + b * 8;
    const uint32_t sb = sbase + 1024 + b * STG;
    mbar_expect_tx(mbar, 16384u);
    const size_t aoff = ((size_t)kn * Mrows + bm0) << 6;   // bytes
    const size_t woff = ((size_t)kn * Nout + bn0) << 6;
    bulk_g2s(sb,        (const char*)A + aoff, 8192, mbar);
    bulk_g2s(sb + 8192, (const char*)W + woff, 8192, mbar);
}

template<int EPI>
__global__ void __launch_bounds__(128, 2) tgemm(
    int K, int Nout,
    const __half* __restrict__ A, const __half* __restrict__ W,
    const float* __restrict__ bias, const float* __restrict__ res,
    float* __restrict__ outf, __half* __restrict__ outh)
{
    extern __shared__ char smem[];
    const uint32_t sbase = smem_u32(smem);
    const int tid  = threadIdx.x;
    const int bn0  = blockIdx.x * 128;
    const int bm0  = blockIdx.y * 128;
    const int warp = tid >> 5, lane = tid & 31;
    const int wm = (warp >> 1) * 64;
    const int wn = (warp & 1) * 64;

    if (tid == 0) {
        #pragma unroll
        for (int s = 0; s < NSTAGE; s++) {
            mbar_init(sbase + s * 8, 1);
            mbar_init(sbase + 32 + s * 8, 128);
        }
        asm volatile("fence.proxy.async.shared::cta;" ::: "memory");
    }
    __syncthreads();

    const int nk = K >> 5;
    if (tid == 0) {
        issue_stage(sbase, 0, 0, Nout, bm0, bn0, A, W);
        issue_stage(sbase, 1, 1, Nout, bm0, bn0, A, W);
        issue_stage(sbase, 2, 2, Nout, bm0, bn0, A, W);
        issue_stage(sbase, 3, 3, Nout, bm0, bn0, A, W);
    }

    float acc[4][8][4];
    #pragma unroll
    for (int mf = 0; mf < 4; mf++)
        #pragma unroll
        for (int nf = 0; nf < 8; nf++)
            #pragma unroll
            for (int u = 0; u < 4; u++) acc[mf][nf][u] = 0.0f;

    const int rA = wm + (lane & 15);
    const int rB = wn + (lane & 15);
    const int cb = lane >> 4;

    for (int kt = 0; kt < nk; kt++) {
        const int b = kt & 3;
        const int cyc = kt >> 2;
        mbar_wait(sbase + b * 8, cyc & 1);

        const uint32_t sg = sbase + 1024 + b * STG;
        const uint32_t at = sg;
        const uint32_t wt = sg + 8192;
        #pragma unroll
        for (int kf = 0; kf < 2; kf++) {
            const int ch = kf * 2 + cb;
            uint32_t a[4][4];
            #pragma unroll
            for (int mf = 0; mf < 4; mf++)
                ldmx4(at + swz((rA + mf * 16) * 64 + ch * 16),
                      a[mf][0], a[mf][1], a[mf][2], a[mf][3]);
            uint32_t b2[8][2];
            #pragma unroll
            for (int n2 = 0; n2 < 4; n2++) {
                uint32_t r0, r1, r2, r3;
                ldmx4(wt + swz((rB + n2 * 16) * 64 + ch * 16), r0, r1, r2, r3);
                b2[2 * n2][0] = r0; b2[2 * n2][1] = r2;
                b2[2 * n2 + 1][0] = r1; b2[2 * n2 + 1][1] = r3;
            }
            #pragma unroll
            for (int mf = 0; mf < 4; mf++)
                #pragma unroll
                for (int nf = 0; nf < 8; nf++)
                    mma16816(acc[mf][nf], a[mf], b2[nf]);
        }
        mbar_arrive(sbase + 32 + b * 8);
        if (tid == 0 && kt + NSTAGE < nk) {
            mbar_wait(sbase + 32 + b * 8, cyc & 1);
            issue_stage(sbase, kt + NSTAGE, b, Nout, bm0, bn0, A, W);
        }
    }

    // ---------------- epilogue ----------------
    const int g = lane >> 2, q = lane & 3;
    #pragma unroll
    for (int mf = 0; mf < 4; mf++) {
        const int row0 = bm0 + wm + mf * 16 + g;
        const int row1 = row0 + 8;
        size_t ob0, ob1;
        if (EPI == EP_PROJ) {
            int bt, l;
            win_to_nat(row0, bt, l); ob0 = ((size_t)bt * Ltok + l) * (size_t)Nout;
            win_to_nat(row1, bt, l); ob1 = ((size_t)bt * Ltok + l) * (size_t)Nout;
        } else {
            ob0 = (size_t)row0 * Nout;
            ob1 = (size_t)row1 * Nout;
        }
        #pragma unroll
        for (int nf = 0; nf < 8; nf++) {
            const int col = bn0 + wn + nf * 8 + q * 2;
            const float b0 = bias[col], b1 = bias[col + 1];
            float v00 = acc[mf][nf][0] + b0, v01 = acc[mf][nf][1] + b1;
            float v10 = acc[mf][nf][2] + b0, v11 = acc[mf][nf][3] + b1;
            if (EPI == EP_BIAS) {
                *(__half2*)(outh + ob0 + col) = __halves2half2(__float2half_rn(v00), __float2half_rn(v01));
                *(__half2*)(outh + ob1 + col) = __halves2half2(__float2half_rn(v10), __float2half_rn(v11));
            } else if (EPI == EP_GELU) {
                v00 = 0.5f * v00 * (1.0f + erff(v00 * 0.70710678118654752f));
                v01 = 0.5f * v01 * (1.0f + erff(v01 * 0.70710678118654752f));
                v10 = 0.5f * v10 * (1.0f + erff(v10 * 0.70710678118654752f));
                v11 = 0.5f * v11 * (1.0f + erff(v11 * 0.70710678118654752f));
                size_t p0 = packed_off(row0, col, Mrows);
                size_t p1 = packed_off(row1, col, Mrows);
                *(__half2*)(outh + p0) = __halves2half2(__float2half_rn(v00), __float2half_rn(v01));
                *(__half2*)(outh + p1) = __halves2half2(__float2half_rn(v10), __float2half_rn(v11));
            } else {  // EP_PROJ / EP_ADD: += residual
                float2 r0 = *(const float2*)(res + ob0 + col);
                float2 r1 = *(const float2*)(res + ob1 + col);
                *(float2*)(outf + ob0 + col) = make_float2(v00 + r0.x, v01 + r0.y);
                *(float2*)(outf + ob1 + col) = make_float2(v10 + r1.x, v11 + r1.y);
            }
        }
    }
}

// ---------------- fused fp32 -> fp16 weight conversion (all 4 weights) ----
__global__ __launch_bounds__(256) void cvt_all(
    const float* __restrict__ wq_s, const float* __restrict__ wp_s,
    const float* __restrict__ w1_s, const float* __restrict__ w2_s,
    __half* __restrict__ wq_d, __half* __restrict__ wp_d,
    __half* __restrict__ w1_d, __half* __restrict__ w2_d)
{
    int i = blockIdx.x * 256 + threadIdx.x;   // global 16B-chunk id
    const float* src;
    __half* dst;
    int Rows, K;
    // chunk counts: wq 98304 | wp 32768 | w1 131072 | w2 131072
    if (i < 98304)       { src = wq_s; dst = wq_d; Rows = 1536; K = 512; }
    else if (i < 131072) { src = wp_s; dst = wp_d; Rows = 512;  K = 512;  i -= 98304; }
    else if (i < 262144) { src = w1_s; dst = w1_d; Rows = 2048; K = 512;  i -= 131072; }
    else                 { src = w2_s; dst = w2_d; Rows = 512;  K = 2048; i -= 262144; }
    int cpr = K >> 3;
    int n = i / cpr;
    int kc = (i - n * cpr) << 3;
    const float4* s = (const float4*)(src + (size_t)n * K + kc);
    float4 v0 = s[0], v1 = s[1];
    float vv[8] = { v0.x, v0.y, v0.z, v0.w, v1.x, v1.y, v1.z, v1.w };
    __half h[8];
    #pragma unroll
    for (int u = 0; u < 8; u++) h[u] = __float2half_rn(vv[u]);
    size_t o = packed_off(n, kc, Rows);
    *(uint4*)(dst + o) = *(uint4*)h;
}

// ---------------- LayerNorm: warp-per-row -> fp16 packed ------------------
__global__ __launch_bounds__(256) void ln_kernel(
    const float* __restrict__ x, const float* __restrict__ g,
    const float* __restrict__ b, __half* __restrict__ outh, int windowed)
{
    const int warp = threadIdx.x >> 5, lane = threadIdx.x & 31;
    const int r = blockIdx.x * 8 + warp;
    size_t ibase;
    if (windowed) {
        int bt, l; win_to_nat(r, bt, l);
        ibase = ((size_t)bt * Ltok + l) * Cdim;
    } else {
        ibase = (size_t)r * Cdim;
    }
    float4 v[4];
    float s = 0.0f, sq = 0.0f;
    #pragma unroll
    for (int i = 0; i < 4; i++) {
        v[i] = *(const float4*)(x + ibase + i * 128 + lane * 4);
        s  += v[i].x + v[i].y + v[i].z + v[i].w;
        sq += v[i].x*v[i].x + v[i].y*v[i].y + v[i].z*v[i].z + v[i].w*v[i].w;
    }
    #pragma unroll
    for (int off = 16; off; off >>= 1) {
        s  += __shfl_xor_sync(0xffffffffu, s,  off);
        sq += __shfl_xor_sync(0xffffffffu, sq, off);
    }
    const float mean = s * (1.0f / 512.0f);
    const float var  = sq * (1.0f / 512.0f) - mean * mean;
    const float rstd = rsqrtf(var + 1e-5f);
    #pragma unroll
    for (int i = 0; i < 4; i++) {
        const int col = i * 128 + lane * 4;
        float4 gg = *(const float4*)(g + col);
        float4 bb = *(const float4*)(b + col);
        __half hv[4];
        hv[0] = __float2half_rn((v[i].x - mean) * rstd * gg.x + bb.x);
        hv[1] = __float2half_rn((v[i].y - mean) * rstd * gg.y + bb.y);
        hv[2] = __float2half_rn((v[i].z - mean) * rstd * gg.z + bb.z);
        hv[3] = __float2half_rn((v[i].w - mean) * rstd * gg.w + bb.w);
        *(uint2*)(outh + packed_off(r, col, Mrows)) = *(uint2*)hv;
    }
}

// ---------------- mma-based windowed attention ----------------------------
#define QSCALE 0.17677669529663687f
#define AZC    0.09817477042468103f
#define RDC    0.02454369260617026f

__global__ __launch_bounds__(128) void attn_kernel(
    const __half* __restrict__ qkv, const float* __restrict__ Dp,
    const float* __restrict__ a_p, const float* __restrict__ b_p,
    const float* __restrict__ a_r, const float* __restrict__ b_r,
    __half* __restrict__ outh)
{
    __shared__ __half Qs[2048];    // 64 x 32, swizzled 64B rows
    __shared__ __half Ks[2048];    // 64 x 32, swizzled 64B rows
    __shared__ __half Vt[2048];    // 32 x 64 (transposed), swizzled 128B rows
    __shared__ float csr[15][64];
    __shared__ float ssr[15][64];
    __shared__ float arh[15], brh[15], phs[15];

    const int wb  = blockIdx.x;
    const int h   = blockIdx.y;
    const int tid = threadIdx.x;
    const int warp = tid >> 5, lane = tid & 31;
    const uint32_t qb = smem_u32(Qs), kb = smem_u32(Ks), vb = smem_u32(Vt);

    // ---- stage Q,K (swizzled rows) and V transposed ----
    {
        const int n = tid >> 1, c0 = (tid & 1) * 2;
        const size_t base = ((size_t)(wb * 64 + n)) * 1536 + h * 32;
        #pragma unroll
        for (int cc = 0; cc < 2; cc++) {
            const int ch = c0 + cc;
            uint4 qv = *(const uint4*)(qkv + base + ch * 8);
            *(uint4*)((char*)Qs + swz(n * 64 + ch * 16)) = qv;
            uint4 kv = *(const uint4*)(qkv + base + 512 + ch * 8);
            *(uint4*)((char*)Ks + swz(n * 64 + ch * 16)) = kv;
            uint4 vv = *(const uint4*)(qkv + base + 1024 + ch * 8);
            const __half* vh = (const __half*)&vv;
            #pragma unroll
            for (int u = 0; u < 8; u++) {
                const int d = ch * 8 + u;
                *(__half*)((char*)Vt + swz(d * 128 + n * 2)) = vh[u];
            }
        }
    }
    {
        int bt = wb >> 6, wi = wb & 63, hb = wi >> 3, wk = wi & 7;
        for (int v = tid; v < 960; v += 128) {
            int dyp = v >> 6, jj = v & 63;
            float Dv = Dp[bt * 4096 + (((hb << 3) + (jj >> 3)) << 6) + (wk << 3) + (jj & 7)];
            float ang = (float)(dyp - 7) * Dv * RDC;
            float sn, cs; __sincosf(ang, &sn, &cs);
            csr[dyp][jj] = cs; ssr[dyp][jj] = sn;
        }
    }
    if (tid < 15) {
        arh[tid] = a_r[tid * NHd + h];
        brh[tid] = b_r[tid * NHd + h];
        int dx = tid - 7;
        int ip = dx < 0 ? dx + 15 : dx;
        float azf = (float)dx * AZC;
        float sn, cs; __sincosf(azf, &sn, &cs);
        phs[tid] = a_p[ip * NHd + h] * cs + b_p[ip * NHd + h] * sn;
    }
    __syncthreads();

    // ---- S = Q K^T (warp: rows 16w..16w+15, all 64 cols) ----
    const int rA = (warp << 4) + (lane & 15);
    const int rN = lane & 15;
    const int cb = lane >> 4;
    float acc[8][4];
    #pragma unroll
    for (int nf = 0; nf < 8; nf++)
        #pragma unroll
        for (int u = 0; u < 4; u++) acc[nf][u] = 0.0f;

    #pragma unroll
    for (int kf = 0; kf < 2; kf++) {
        const int ch = kf * 2 + cb;
        uint32_t a[4];
        ldmx4(qb + swz(rA * 64 + ch * 16), a[0], a[1], a[2], a[3]);
        uint32_t b2[8][2];
        #pragma unroll
        for (int n2 = 0; n2 < 4; n2++) {
            uint32_t r0, r1, r2, r3;
            ldmx4(kb + swz((n2 * 16 + rN) * 64 + ch * 16), r0, r1, r2, r3);
            b2[2 * n2][0] = r0; b2[2 * n2][1] = r2;
            b2[2 * n2 + 1][0] = r1; b2[2 * n2 + 1][1] = r3;
        }
        #pragma unroll
        for (int nf = 0; nf < 8; nf++)
            mma16816(acc[nf], a, b2[nf]);
    }

    // ---- scale + bias (frag mapping: rows 16w+g, 16w+g+8; col nf*8+2q(+1)) ----
    const int g = lane >> 2, q = lane & 3;
    const float ph0 = phs[g - 2 * q + 7];
    const float ph1 = phs[g - 2 * q + 6];
    #pragma unroll
    for (int nf = 0; nf < 8; nf++) {
        const int dy0 = 2 * warp - nf;
        const int dyp0 = dy0 + 7, ir0 = dy0 < 0 ? dy0 + 15 : dy0;
        const int dy1 = dy0 + 1;
        const int dyp1 = dy1 + 7, ir1 = dy1 < 0 ? dy1 + 15 : dy1;
        const int jA = nf * 8 + 2 * q, jB = jA + 1;
        acc[nf][0] = acc[nf][0] * QSCALE + ph0 + arh[ir0] * csr[dyp0][jA] + brh[ir0] * ssr[dyp0][jA];
        acc[nf][1] = acc[nf][1] * QSCALE + ph1 + arh[ir0] * csr[dyp0][jB] + brh[ir0] * ssr[dyp0][jB];
        acc[nf][2] = acc[nf][2] * QSCALE + ph0 + arh[ir1] * csr[dyp1][jA] + brh[ir1] * ssr[dyp1][jA];
        acc[nf][3] = acc[nf][3] * QSCALE + ph1 + arh[ir1] * csr[dyp1][jB] + brh[ir1] * ssr[dyp1][jB];
    }

    // ---- softmax (rows owned by one warp; reduce across the 4 q-lanes) ----
    float mx0 = -1e30f, mx1 = -1e30f;
    #pragma unroll
    for (int nf = 0; nf < 8; nf++) {
        mx0 = fmaxf(mx0, fmaxf(acc[nf][0], acc[nf][1]));
        mx1 = fmaxf(mx1, fmaxf(acc[nf][2], acc[nf][3]));
    }
    mx0 = fmaxf(mx0, __shfl_xor_sync(0xffffffffu, mx0, 1));
    mx0 = fmaxf(mx0, __shfl_xor_sync(0xffffffffu, mx0, 2));
    mx1 = fmaxf(mx1, __shfl_xor_sync(0xffffffffu, mx1, 1));
    mx1 = fmaxf(mx1, __shfl_xor_sync(0xffffffffu, mx1, 2));
    float s0 = 0.0f, s1 = 0.0f;
    #pragma unroll
    for (int nf = 0; nf < 8; nf++) {
        acc[nf][0] = __expf(acc[nf][0] - mx0); s0 += acc[nf][0];
        acc[nf][1] = __expf(acc[nf][1] - mx0); s0 += acc[nf][1];
        acc[nf][2] = __expf(acc[nf][2] - mx1); s1 += acc[nf][2];
        acc[nf][3] = __expf(acc[nf][3] - mx1); s1 += acc[nf][3];
    }
    s0 += __shfl_xor_sync(0xffffffffu, s0, 1);
    s0 += __shfl_xor_sync(0xffffffffu, s0, 2);
    s1 += __shfl_xor_sync(0xffffffffu, s1, 1);
    s1 += __shfl_xor_sync(0xffffffffu, s1, 2);
    const float inv0 = 1.0f / s0, inv1 = 1.0f / s1;

    // ---- repack P (C frags -> fp16 A frags) ----
    uint32_t p[4][4];
    #pragma unroll
    for (int kt = 0; kt < 4; kt++) {
        __half2 h0 = __floats2half2_rn(acc[2 * kt][0] * inv0,     acc[2 * kt][1] * inv0);
        __half2 h1 = __floats2half2_rn(acc[2 * kt][2] * inv1,     acc[2 * kt][3] * inv1);
        __half2 h2 = __floats2half2_rn(acc[2 * kt + 1][0] * inv0, acc[2 * kt + 1][1] * inv0);
        __half2 h3 = __floats2half2_rn(acc[2 * kt + 1][2] * inv1, acc[2 * kt + 1][3] * inv1);
        p[kt][0] = *(uint32_t*)&h0; p[kt][1] = *(uint32_t*)&h1;
        p[kt][2] = *(uint32_t*)&h2; p[kt][3] = *(uint32_t*)&h3;
    }

    // ---- O = P V (B frags from V^T) ----
    float oacc[4][4];
    #pragma unroll
    for (int nf2 = 0; nf2 < 4; nf2++)
        #pragma unroll
        for (int u = 0; u < 4; u++) oacc[nf2][u] = 0.0f;
    #pragma unroll
    for (int kt = 0; kt < 4; kt++) {
        uint32_t bv[4][2];
        #pragma unroll
        for (int n2 = 0; n2 < 2; n2++) {
            uint32_t r0, r1, r2, r3;
            ldmx4(vb + swz((n2 * 16 + rN) * 128 + (kt * 2 + cb) * 16), r0, r1, r2, r3);
            bv[2 * n2][0] = r0; bv[2 * n2][1] = r2;
            bv[2 * n2 + 1][0] = r1; bv[2 * n2 + 1][1] = r3;
        }
        #pragma unroll
        for (int nf2 = 0; nf2 < 4; nf2++)
            mma16816(oacc[nf2], p[kt], bv[nf2]);
    }

    // ---- store O -> packed fp16 ----
    const int i0 = (warp << 4) + g;
    const int row0 = wb * 64 + i0, row1 = row0 + 8;
    #pragma unroll
    for (int nf2 = 0; nf2 < 4; nf2++) {
        const int d = h * 32 + nf2 * 8 + 2 * q;
        *(__half2*)(outh + packed_off(row0, d, Mrows)) =
            __floats2half2_rn(oacc[nf2][0], oacc[nf2][1]);
        *(__half2*)(outh + packed_off(row1, d, Mrows)) =
            __floats2half2_rn(oacc[nf2][2], oacc[nf2][3]);
    }
}

// ---------------- launch -------------------------------------------------
extern "C" void kernel_launch(void* const* d_in, const int* in_sizes, int n_in,
                              void* d_out, int out_size) {
    (void)in_sizes; (void)n_in; (void)out_size;
    const float* x      = (const float*)d_in[0];
    const float* D      = (const float*)d_in[1];
    const float* n1g    = (const float*)d_in[2];
    const float* n1b    = (const float*)d_in[3];
    const float* qkv_w  = (const float*)d_in[4];
    const float* qkv_b  = (const float*)d_in[5];
    const float* proj_w = (const float*)d_in[6];
    const float* proj_b = (const float*)d_in[7];
    const float* a_p    = (const float*)d_in[8];
    const float* b_p    = (const float*)d_in[9];
    const float* a_r    = (const float*)d_in[10];
    const float* b_r    = (const float*)d_in[11];
    const float* n2g    = (const float*)d_in[12];
    const float* n2b    = (const float*)d_in[13];
    const float* fc1_w  = (const float*)d_in[14];
    const float* fc1_b  = (const float*)d_in[15];
    const float* fc2_w  = (const float*)d_in[16];
    const float* fc2_b  = (const float*)d_in[17];
    float* out = (float*)d_out;

    __half *xw, *qkvh, *at, *xm, *hb, *wq, *wp, *w1, *w2;
    float *x2;
    cudaGetSymbolAddress((void**)&xw, g_xw);
    cudaGetSymbolAddress((void**)&qkvh, g_qkvh);
    cudaGetSymbolAddress((void**)&at, g_at);
    cudaGetSymbolAddress((void**)&xm, g_xm);
    cudaGetSymbolAddress((void**)&hb, g_h);
    cudaGetSymbolAddress((void**)&wq, g_wq);
    cudaGetSymbolAddress((void**)&wp, g_wp);
    cudaGetSymbolAddress((void**)&w1, g_w1);
    cudaGetSymbolAddress((void**)&w2, g_w2);
    cudaGetSymbolAddress((void**)&x2, g_x2);

    cudaFuncSetAttribute(tgemm<EP_BIAS>, cudaFuncAttributeMaxDynamicSharedMemorySize, SMEM_TOT);
    cudaFuncSetAttribute(tgemm<EP_GELU>, cudaFuncAttributeMaxDynamicSharedMemorySize, SMEM_TOT);
    cudaFuncSetAttribute(tgemm<EP_PROJ>, cudaFuncAttributeMaxDynamicSharedMemorySize, SMEM_TOT);
    cudaFuncSetAttribute(tgemm<EP_ADD>,  cudaFuncAttributeMaxDynamicSharedMemorySize, SMEM_TOT);

    // fused weight conversion (4 weights, one launch; 393216 chunks)
    cvt_all<<<393216 / 256, 256>>>(qkv_w, proj_w, fc1_w, fc2_w, wq, wp, w1, w2);

    // 1) LN1 + window partition -> packed fp16
    ln_kernel<<<Mrows / 8, 256>>>(x, n1g, n1b, xw, 1);
    // 2) QKV GEMM -> fp16 natural
    tgemm<EP_BIAS><<<dim3(1536 / 128, Mrows / 128), 128, SMEM_TOT>>>(
        512, 1536, xw, wq, qkv_b, nullptr, nullptr, qkvh);
    // 3) mma windowed attention -> packed fp16
    attn_kernel<<<dim3(1024, 16), 128>>>(qkvh, D, a_p, b_p, a_r, b_r, at);
    // 4) proj GEMM + window reverse + residual
    tgemm<EP_PROJ><<<dim3(512 / 128, Mrows / 128), 128, SMEM_TOT>>>(
        512, 512, at, wp, proj_b, x, x2, nullptr);
    // 5) LN2 -> packed fp16
    ln_kernel<<<Mrows / 8, 256>>>(x2, n2g, n2b, xm, 0);
    // 6) fc1 + GELU -> packed fp16
    tgemm<EP_GELU><<<dim3(2048 / 128, Mrows / 128), 128, SMEM_TOT>>>(
        512, 2048, xm, w1, fc1_b, nullptr, nullptr, hb);
    // 7) fc2 + residual -> output
    tgemm<EP_ADD><<<dim3(512 / 128, Mrows / 128), 128, SMEM_TOT>>>(
        2048, 512, hb, w2, fc2_b, x2, out, nullptr);
}